// round 2
// baseline (speedup 1.0000x reference)
#include <cuda_runtime.h>

// Problem constants
#define BATCH 8
#define LEN   512
#define DIM   768
#define MAXW  12
#define NSPAN (LEN * MAXW)          // 6144
#define MROWS (BATCH * LEN)         // 4096 (GEMM M)
// All 4 GEMMs are MROWS x DIM x DIM (M=4096, N=768, K=768)

// Scratch (static __device__ arrays — no allocation allowed)
__device__ float g_S[MROWS * DIM];  // relu(h@Ws + bs)
__device__ float g_E[MROWS * DIM];  // relu(h@We + be)
__device__ float g_P[MROWS * DIM];  // S @ Wo_top
__device__ float g_Q[MROWS * DIM];  // E @ Wo_bot

// ---------------------------------------------------------------------------
// Tiled fp32 SGEMM: C[M,N] = op(A[M,K] @ W[K,N] + bias)
// BM=128, BN=128, BK=16, 256 threads, 8x8 accum per thread.
// M=4096, N=768, K=768 fixed.
// ---------------------------------------------------------------------------
template <bool RELU_BIAS>
__device__ __forceinline__ void sgemm_body(
    const float* __restrict__ A,
    const float* __restrict__ W,
    const float* __restrict__ bias,
    float* __restrict__ C)
{
    constexpr int BM = 128, BN = 128, BK = 16;
    __shared__ float As[BK][BM];      // transposed A tile
    __shared__ float Bs[BK][BN];

    const int tid = threadIdx.x;
    const int bm = blockIdx.y * BM;
    const int bn = blockIdx.x * BN;
    const int tx = tid & 15;          // 0..15 -> N
    const int ty = tid >> 4;          // 0..15 -> M

    // A tile load mapping: 128 rows x 16 cols = 512 float4, 2 per thread
    const int a_row  = tid >> 2;      // 0..63
    const int a_col  = (tid & 3) * 4; // 0,4,8,12
    // B tile load mapping: 16 rows x 128 cols = 512 float4, 2 per thread
    const int b_row  = tid >> 5;      // 0..7
    const int b_col  = (tid & 31) * 4;

    float acc[8][8];
#pragma unroll
    for (int i = 0; i < 8; i++)
#pragma unroll
        for (int j = 0; j < 8; j++) acc[i][j] = 0.0f;

    for (int k0 = 0; k0 < DIM; k0 += BK) {
        // Load A tile (transpose into As[k][m])
#pragma unroll
        for (int p = 0; p < 2; p++) {
            const int r = a_row + p * 64;
            float4 v = *(const float4*)&A[(size_t)(bm + r) * DIM + k0 + a_col];
            As[a_col + 0][r] = v.x;
            As[a_col + 1][r] = v.y;
            As[a_col + 2][r] = v.z;
            As[a_col + 3][r] = v.w;
        }
        // Load B tile
#pragma unroll
        for (int p = 0; p < 2; p++) {
            const int r = b_row + p * 8;
            *(float4*)&Bs[r][b_col] =
                *(const float4*)&W[(size_t)(k0 + r) * DIM + bn + b_col];
        }
        __syncthreads();

#pragma unroll
        for (int k = 0; k < BK; k++) {
            float4 a0 = *(const float4*)&As[k][ty * 8];
            float4 a1 = *(const float4*)&As[k][ty * 8 + 4];
            float4 b0 = *(const float4*)&Bs[k][tx * 8];
            float4 b1 = *(const float4*)&Bs[k][tx * 8 + 4];
            float a[8] = {a0.x, a0.y, a0.z, a0.w, a1.x, a1.y, a1.z, a1.w};
            float b[8] = {b0.x, b0.y, b0.z, b0.w, b1.x, b1.y, b1.z, b1.w};
#pragma unroll
            for (int i = 0; i < 8; i++)
#pragma unroll
                for (int j = 0; j < 8; j++)
                    acc[i][j] = fmaf(a[i], b[j], acc[i][j]);
        }
        __syncthreads();
    }

    // Epilogue
#pragma unroll
    for (int i = 0; i < 8; i++) {
        const int m = bm + ty * 8 + i;
#pragma unroll
        for (int j = 0; j < 8; j += 4) {
            const int n = bn + tx * 8 + j;
            float4 v;
            v.x = acc[i][j + 0];
            v.y = acc[i][j + 1];
            v.z = acc[i][j + 2];
            v.w = acc[i][j + 3];
            if (RELU_BIAS) {
                v.x = fmaxf(v.x + bias[n + 0], 0.0f);
                v.y = fmaxf(v.y + bias[n + 1], 0.0f);
                v.z = fmaxf(v.z + bias[n + 2], 0.0f);
                v.w = fmaxf(v.w + bias[n + 3], 0.0f);
            }
            *(float4*)&C[(size_t)m * DIM + n] = v;
        }
    }
}

// Stage 1: z=0 -> S = relu(h@Ws+bs), z=1 -> E = relu(h@We+be)
__global__ __launch_bounds__(256, 2)
void stage1_kernel(const float* __restrict__ h,
                   const float* __restrict__ Ws, const float* __restrict__ bs,
                   const float* __restrict__ We, const float* __restrict__ be)
{
    if (blockIdx.z == 0)
        sgemm_body<true>(h, Ws, bs, g_S);
    else
        sgemm_body<true>(h, We, be, g_E);
}

// Stage 2: z=0 -> P = S@Wo_top, z=1 -> Q = E@Wo_bot
__global__ __launch_bounds__(256, 2)
void stage2_kernel(const float* __restrict__ Wo)
{
    if (blockIdx.z == 0)
        sgemm_body<false>(g_S, Wo, nullptr, g_P);
    else
        sgemm_body<false>(g_E, Wo + DIM * DIM, nullptr, g_Q);
}

// Stage 3: out[b,n,:] = P[b, idx_s] + Q[b, idx_e] + bo
// NOTE: span_idx is int32 on device (JAX x64 disabled -> int64 request
// silently becomes int32).
// One (192,4) block handles 4 rows; 192 threads x float4 = 768 floats per row.
__global__ void gather_add_kernel(const int* __restrict__ span_idx,
                                  const float* __restrict__ bo,
                                  float* __restrict__ out)
{
    const int row = blockIdx.x * 4 + threadIdx.y;   // 0 .. B*N-1
    const int b = row / NSPAN;
    const int is = span_idx[(size_t)row * 2 + 0];
    const int ie = span_idx[(size_t)row * 2 + 1];
    const int t = threadIdx.x;                      // 0..191

    const float4* p = (const float4*)(g_P + (size_t)(b * LEN + is) * DIM);
    const float4* q = (const float4*)(g_Q + (size_t)(b * LEN + ie) * DIM);
    const float4* bo4 = (const float4*)bo;
    float4* o = (float4*)(out + (size_t)row * DIM);

    float4 pv = p[t];
    float4 qv = q[t];
    float4 bv = __ldg(&bo4[t]);
    o[t] = make_float4(pv.x + qv.x + bv.x,
                       pv.y + qv.y + bv.y,
                       pv.z + qv.z + bv.z,
                       pv.w + qv.w + bv.w);
}

extern "C" void kernel_launch(void* const* d_in, const int* in_sizes, int n_in,
                              void* d_out, int out_size)
{
    (void)in_sizes; (void)n_in; (void)out_size;
    const float* h    = (const float*)d_in[0];
    const int*   span = (const int*)d_in[1];
    const float* Ws   = (const float*)d_in[2];
    const float* bs   = (const float*)d_in[3];
    const float* We   = (const float*)d_in[4];
    const float* be   = (const float*)d_in[5];
    const float* Wo   = (const float*)d_in[6];
    const float* bo   = (const float*)d_in[7];
    float* out = (float*)d_out;

    dim3 gemm_grid(DIM / 128, MROWS / 128, 2);   // (6, 32, 2)
    stage1_kernel<<<gemm_grid, 256>>>(h, Ws, bs, We, be);
    stage2_kernel<<<gemm_grid, 256>>>(Wo);

    dim3 gblock(192, 4);
    gather_add_kernel<<<(BATCH * NSPAN) / 4, gblock>>>(span, bo, out);
}

// round 5
// speedup vs baseline: 2.2896x; 2.2896x over previous
#include <cuda_runtime.h>
#include <cuda_bf16.h>
#include <cstdint>

#define BATCH 8
#define LEN   512
#define DIM   768
#define MAXW  12
#define NSPAN (LEN * MAXW)          // 6144
#define MROWS (BATCH * LEN)         // 4096

// ---------------------------------------------------------------------------
// Scratch (static device arrays; no allocation allowed)
// ---------------------------------------------------------------------------
__device__ __nv_bfloat16 g_h_hi[MROWS * DIM];
__device__ __nv_bfloat16 g_h_lo[MROWS * DIM];
__device__ __nv_bfloat16 g_S_hi[MROWS * DIM];
__device__ __nv_bfloat16 g_S_lo[MROWS * DIM];
__device__ __nv_bfloat16 g_E_hi[MROWS * DIM];
__device__ __nv_bfloat16 g_E_lo[MROWS * DIM];
// Packed weights: [0]=Ws, [1]=We, [2]=Wo_top, [3]=Wo_bot (each DIM*DIM, [K][N])
__device__ __nv_bfloat16 g_W_hi[4 * DIM * DIM];
__device__ __nv_bfloat16 g_W_lo[4 * DIM * DIM];
__device__ float g_P[MROWS * DIM];
__device__ float g_Q[MROWS * DIM];

// ---------------------------------------------------------------------------
// fp32 -> (bf16 hi, bf16 lo) split.
// blockIdx.y: 0 = h (n4=786432 -> 3072 blocks), 1 = Ws, 2 = We, 3 = Wo (both halves).
// ---------------------------------------------------------------------------
__global__ void split_all_kernel(const float* __restrict__ h,
                                 const float* __restrict__ Ws,
                                 const float* __restrict__ We,
                                 const float* __restrict__ Wo)
{
    const int region = blockIdx.y;
    const float* src;
    __nv_bfloat16 *hi, *lo;
    int n4;
    const int W4 = (DIM * DIM) / 4;   // 147456
    switch (region) {
        case 0: src = h;  hi = g_h_hi;                 lo = g_h_lo;                 n4 = (MROWS * DIM) / 4; break; // 786432
        case 1: src = Ws; hi = g_W_hi;                 lo = g_W_lo;                 n4 = W4; break;
        case 2: src = We; hi = g_W_hi + DIM * DIM;     lo = g_W_lo + DIM * DIM;     n4 = W4; break;
        default: src = Wo; hi = g_W_hi + 2 * DIM * DIM; lo = g_W_lo + 2 * DIM * DIM; n4 = 2 * W4; break;
    }
    int i = blockIdx.x * blockDim.x + threadIdx.x;
    if (i >= n4) return;
    float4 v = ((const float4*)src)[i];
    __nv_bfloat16 h0 = __float2bfloat16(v.x);
    __nv_bfloat16 h1 = __float2bfloat16(v.y);
    __nv_bfloat16 h2 = __float2bfloat16(v.z);
    __nv_bfloat16 h3 = __float2bfloat16(v.w);
    __nv_bfloat16 l0 = __float2bfloat16(v.x - __bfloat162float(h0));
    __nv_bfloat16 l1 = __float2bfloat16(v.y - __bfloat162float(h1));
    __nv_bfloat16 l2 = __float2bfloat16(v.z - __bfloat162float(h2));
    __nv_bfloat16 l3 = __float2bfloat16(v.w - __bfloat162float(h3));
    ((__nv_bfloat162*)hi)[i * 2 + 0] = __nv_bfloat162(h0, h1);
    ((__nv_bfloat162*)hi)[i * 2 + 1] = __nv_bfloat162(h2, h3);
    ((__nv_bfloat162*)lo)[i * 2 + 0] = __nv_bfloat162(l0, l1);
    ((__nv_bfloat162*)lo)[i * 2 + 1] = __nv_bfloat162(l2, l3);
}

// ---------------------------------------------------------------------------
// MMA helpers
// ---------------------------------------------------------------------------
__device__ __forceinline__ void ldsm_x4(uint32_t* r, uint32_t addr)
{
    asm volatile("ldmatrix.sync.aligned.m8n8.x4.shared.b16 {%0,%1,%2,%3}, [%4];"
                 : "=r"(r[0]), "=r"(r[1]), "=r"(r[2]), "=r"(r[3]) : "r"(addr));
}
__device__ __forceinline__ void ldsm_x4_t(uint32_t* r, uint32_t addr)
{
    asm volatile("ldmatrix.sync.aligned.m8n8.x4.trans.shared.b16 {%0,%1,%2,%3}, [%4];"
                 : "=r"(r[0]), "=r"(r[1]), "=r"(r[2]), "=r"(r[3]) : "r"(addr));
}
__device__ __forceinline__ void mma_bf16(float* c, const uint32_t* a, const uint32_t* b)
{
    asm volatile("mma.sync.aligned.m16n8k16.row.col.f32.bf16.bf16.f32 "
                 "{%0,%1,%2,%3}, {%4,%5,%6,%7}, {%8,%9}, {%0,%1,%2,%3};"
                 : "+f"(c[0]), "+f"(c[1]), "+f"(c[2]), "+f"(c[3])
                 : "r"(a[0]), "r"(a[1]), "r"(a[2]), "r"(a[3]), "r"(b[0]), "r"(b[1]));
}

// ---------------------------------------------------------------------------
// 3-split bf16 tensor-core GEMM body.
// C[M,N] = A[M,K] @ W[K,N], M=4096, N=768, K=768.
// BM=128, BN=128, BK=32. 256 threads = 8 warps (2 m x 4 n), warp tile 64x32.
// STAGE1: epilogue = relu(acc + bias) -> write split bf16 (Ohi, Olo)
// else:   epilogue = write fp32 Of
// ---------------------------------------------------------------------------
template <bool STAGE1>
__device__ __forceinline__ void gemm3_body(
    const __nv_bfloat16* __restrict__ Ahi, const __nv_bfloat16* __restrict__ Alo,
    const __nv_bfloat16* __restrict__ Whi, const __nv_bfloat16* __restrict__ Wlo,
    const float* __restrict__ bias,
    __nv_bfloat16* __restrict__ Ohi, __nv_bfloat16* __restrict__ Olo,
    float* __restrict__ Of)
{
    constexpr int BM = 128, BN = 128, BK = 32;
    constexpr int ASTR = BK + 8;    // 40, conflict-free for ldmatrix
    constexpr int BSTR = BN + 8;    // 136, conflict-free for ldmatrix.trans

    __shared__ __nv_bfloat16 sAhi[BM][ASTR];
    __shared__ __nv_bfloat16 sAlo[BM][ASTR];
    __shared__ __nv_bfloat16 sBhi[BK][BSTR];
    __shared__ __nv_bfloat16 sBlo[BK][BSTR];

    const int tid  = threadIdx.x;
    const int lane = tid & 31;
    const int w    = tid >> 5;
    const int wm   = (w >> 2) * 64;   // warp m offset in tile
    const int wn   = (w & 3) * 32;    // warp n offset in tile
    const int bm   = blockIdx.y * BM;
    const int bn   = blockIdx.x * BN;

    float acc[4][4][4];
#pragma unroll
    for (int i = 0; i < 4; i++)
#pragma unroll
        for (int j = 0; j < 4; j++)
#pragma unroll
            for (int k = 0; k < 4; k++) acc[i][j][k] = 0.0f;

    for (int k0 = 0; k0 < DIM; k0 += BK) {
        // Load A tiles: 128x32 per split = 1024 8B-chunks, 4 per thread
#pragma unroll
        for (int i = 0; i < 4; i++) {
            int c = tid + i * 256;
            int row = c >> 3, col = (c & 7) * 4;
            size_t g = (size_t)(bm + row) * DIM + k0 + col;
            *(uint2*)&sAhi[row][col] = *(const uint2*)&Ahi[g];
            *(uint2*)&sAlo[row][col] = *(const uint2*)&Alo[g];
        }
        // Load B tiles: 32x128 per split = 1024 8B-chunks, 4 per thread
#pragma unroll
        for (int i = 0; i < 4; i++) {
            int c = tid + i * 256;
            int row = c >> 5, col = (c & 31) * 4;
            size_t g = (size_t)(k0 + row) * DIM + bn + col;
            *(uint2*)&sBhi[row][col] = *(const uint2*)&Whi[g];
            *(uint2*)&sBlo[row][col] = *(const uint2*)&Wlo[g];
        }
        __syncthreads();

#pragma unroll
        for (int kk = 0; kk < BK; kk += 16) {
            uint32_t a_hi[4][4], a_lo[4][4], b_hi[4][2], b_lo[4][2];
            // A fragments: 4 m16 tiles
#pragma unroll
            for (int mi = 0; mi < 4; mi++) {
                int row = wm + mi * 16 + (lane & 15);
                int col = kk + (lane >> 4) * 8;
                ldsm_x4(a_hi[mi], (uint32_t)__cvta_generic_to_shared(&sAhi[row][col]));
                ldsm_x4(a_lo[mi], (uint32_t)__cvta_generic_to_shared(&sAlo[row][col]));
            }
            // B fragments: 2 x (k16 x n16) -> 4 n8 tiles
#pragma unroll
            for (int ni = 0; ni < 2; ni++) {
                int row = kk + (lane & 15);
                int col = wn + ni * 16 + (lane >> 4) * 8;
                uint32_t rh[4], rl[4];
                ldsm_x4_t(rh, (uint32_t)__cvta_generic_to_shared(&sBhi[row][col]));
                ldsm_x4_t(rl, (uint32_t)__cvta_generic_to_shared(&sBlo[row][col]));
                b_hi[ni * 2][0] = rh[0]; b_hi[ni * 2][1] = rh[1];
                b_hi[ni * 2 + 1][0] = rh[2]; b_hi[ni * 2 + 1][1] = rh[3];
                b_lo[ni * 2][0] = rl[0]; b_lo[ni * 2][1] = rl[1];
                b_lo[ni * 2 + 1][0] = rl[2]; b_lo[ni * 2 + 1][1] = rl[3];
            }
            // 3-split products
#pragma unroll
            for (int mi = 0; mi < 4; mi++)
#pragma unroll
                for (int nj = 0; nj < 4; nj++) {
                    mma_bf16(acc[mi][nj], a_hi[mi], b_hi[nj]);
                    mma_bf16(acc[mi][nj], a_hi[mi], b_lo[nj]);
                    mma_bf16(acc[mi][nj], a_lo[mi], b_hi[nj]);
                }
        }
        __syncthreads();
    }

    // Epilogue. c-frag layout: c0,c1 -> (row=lane>>2, col=(lane&3)*2 + {0,1});
    // c2,c3 -> row+8.
    const int er = lane >> 2;
    const int ec = (lane & 3) * 2;
#pragma unroll
    for (int mi = 0; mi < 4; mi++) {
#pragma unroll
        for (int nj = 0; nj < 4; nj++) {
            int m0 = bm + wm + mi * 16 + er;
            int n0 = bn + wn + nj * 8 + ec;
            float v0 = acc[mi][nj][0], v1 = acc[mi][nj][1];
            float v2 = acc[mi][nj][2], v3 = acc[mi][nj][3];
            if (STAGE1) {
                float b0 = bias[n0], b1 = bias[n0 + 1];
                v0 = fmaxf(v0 + b0, 0.0f); v1 = fmaxf(v1 + b1, 0.0f);
                v2 = fmaxf(v2 + b0, 0.0f); v3 = fmaxf(v3 + b1, 0.0f);
                __nv_bfloat16 h0 = __float2bfloat16(v0), h1 = __float2bfloat16(v1);
                __nv_bfloat16 h2 = __float2bfloat16(v2), h3 = __float2bfloat16(v3);
                __nv_bfloat16 l0 = __float2bfloat16(v0 - __bfloat162float(h0));
                __nv_bfloat16 l1 = __float2bfloat16(v1 - __bfloat162float(h1));
                __nv_bfloat16 l2 = __float2bfloat16(v2 - __bfloat162float(h2));
                __nv_bfloat16 l3 = __float2bfloat16(v3 - __bfloat162float(h3));
                *(__nv_bfloat162*)&Ohi[(size_t)m0 * DIM + n0] = __nv_bfloat162(h0, h1);
                *(__nv_bfloat162*)&Olo[(size_t)m0 * DIM + n0] = __nv_bfloat162(l0, l1);
                *(__nv_bfloat162*)&Ohi[(size_t)(m0 + 8) * DIM + n0] = __nv_bfloat162(h2, h3);
                *(__nv_bfloat162*)&Olo[(size_t)(m0 + 8) * DIM + n0] = __nv_bfloat162(l2, l3);
            } else {
                *(float2*)&Of[(size_t)m0 * DIM + n0] = make_float2(v0, v1);
                *(float2*)&Of[(size_t)(m0 + 8) * DIM + n0] = make_float2(v2, v3);
            }
        }
    }
}

__global__ __launch_bounds__(256)
void stage1_kernel(const float* __restrict__ bs, const float* __restrict__ be)
{
    if (blockIdx.z == 0)
        gemm3_body<true>(g_h_hi, g_h_lo, g_W_hi, g_W_lo, bs,
                         g_S_hi, g_S_lo, nullptr);
    else
        gemm3_body<true>(g_h_hi, g_h_lo, g_W_hi + DIM * DIM, g_W_lo + DIM * DIM, be,
                         g_E_hi, g_E_lo, nullptr);
}

__global__ __launch_bounds__(256)
void stage2_kernel()
{
    if (blockIdx.z == 0)
        gemm3_body<false>(g_S_hi, g_S_lo, g_W_hi + 2 * DIM * DIM, g_W_lo + 2 * DIM * DIM,
                          nullptr, nullptr, nullptr, g_P);
    else
        gemm3_body<false>(g_E_hi, g_E_lo, g_W_hi + 3 * DIM * DIM, g_W_lo + 3 * DIM * DIM,
                          nullptr, nullptr, nullptr, g_Q);
}

// ---------------------------------------------------------------------------
// Gather-add: out[b,n,:] = P[b, idx_s] + Q[b, idx_e] + bo
// span_idx is int32 on device (JAX x64 disabled).
// ---------------------------------------------------------------------------
__global__ void gather_add_kernel(const int* __restrict__ span_idx,
                                  const float* __restrict__ bo,
                                  float* __restrict__ out)
{
    const int row = blockIdx.x * 4 + threadIdx.y;   // 0 .. B*N-1
    const int b = row / NSPAN;
    const int is = span_idx[(size_t)row * 2 + 0];
    const int ie = span_idx[(size_t)row * 2 + 1];
    const int t = threadIdx.x;                      // 0..191

    const float4* p = (const float4*)(g_P + (size_t)(b * LEN + is) * DIM);
    const float4* q = (const float4*)(g_Q + (size_t)(b * LEN + ie) * DIM);
    const float4* bo4 = (const float4*)bo;
    float4* o = (float4*)(out + (size_t)row * DIM);

    float4 pv = p[t];
    float4 qv = q[t];
    float4 bv = __ldg(&bo4[t]);
    o[t] = make_float4(pv.x + qv.x + bv.x,
                       pv.y + qv.y + bv.y,
                       pv.z + qv.z + bv.z,
                       pv.w + qv.w + bv.w);
}

extern "C" void kernel_launch(void* const* d_in, const int* in_sizes, int n_in,
                              void* d_out, int out_size)
{
    (void)in_sizes; (void)n_in; (void)out_size;
    const float* h    = (const float*)d_in[0];
    const int*   span = (const int*)d_in[1];
    const float* Ws   = (const float*)d_in[2];
    const float* bs   = (const float*)d_in[3];
    const float* We   = (const float*)d_in[4];
    const float* be   = (const float*)d_in[5];
    const float* Wo   = (const float*)d_in[6];
    const float* bo   = (const float*)d_in[7];
    float* out = (float*)d_out;

    // Split grid must cover the LARGEST region: h with n4 = 786432 -> 3072 blocks.
    // (R4 bug: launched 1152 and left 62% of g_h_hi/lo zero.)
    {
        dim3 sgrid(3072, 4);
        split_all_kernel<<<sgrid, 256>>>(h, Ws, We, Wo);
    }

    dim3 gemm_grid(DIM / 128, MROWS / 128, 2);   // (6, 32, 2)
    stage1_kernel<<<gemm_grid, 256>>>(bs, be);
    stage2_kernel<<<gemm_grid, 256>>>();

    dim3 gblock(192, 4);
    gather_add_kernel<<<(BATCH * NSPAN) / 4, gblock>>>(span, bo, out);
}

// round 6
// speedup vs baseline: 2.5068x; 1.0949x over previous
#include <cuda_runtime.h>
#include <cuda_bf16.h>
#include <cstdint>

#define BATCH 8
#define LEN   512
#define DIM   768
#define MAXW  12
#define NSPAN (LEN * MAXW)          // 6144
#define MROWS (BATCH * LEN)         // 4096

// ---------------------------------------------------------------------------
// Scratch (static device arrays; no allocation allowed)
// ---------------------------------------------------------------------------
__device__ __nv_bfloat16 g_h_hi[MROWS * DIM];
__device__ __nv_bfloat16 g_h_lo[MROWS * DIM];
__device__ __nv_bfloat16 g_S_hi[MROWS * DIM];
__device__ __nv_bfloat16 g_S_lo[MROWS * DIM];
__device__ __nv_bfloat16 g_E_hi[MROWS * DIM];
__device__ __nv_bfloat16 g_E_lo[MROWS * DIM];
// Packed weights: [0]=Ws, [1]=We, [2]=Wo_top, [3]=Wo_bot (each DIM*DIM, [K][N])
__device__ __nv_bfloat16 g_W_hi[4 * DIM * DIM];
__device__ __nv_bfloat16 g_W_lo[4 * DIM * DIM];
__device__ float g_P[MROWS * DIM];
__device__ float g_Q[MROWS * DIM];

// ---------------------------------------------------------------------------
// fp32 -> (bf16 hi, bf16 lo) split.
// blockIdx.y: 0 = h (n4=786432 -> 3072 blocks), 1 = Ws, 2 = We, 3 = Wo.
// ---------------------------------------------------------------------------
__global__ void split_all_kernel(const float* __restrict__ h,
                                 const float* __restrict__ Ws,
                                 const float* __restrict__ We,
                                 const float* __restrict__ Wo)
{
    const int region = blockIdx.y;
    const float* src;
    __nv_bfloat16 *hi, *lo;
    int n4;
    const int W4 = (DIM * DIM) / 4;   // 147456
    switch (region) {
        case 0: src = h;  hi = g_h_hi;                 lo = g_h_lo;                 n4 = (MROWS * DIM) / 4; break; // 786432
        case 1: src = Ws; hi = g_W_hi;                 lo = g_W_lo;                 n4 = W4; break;
        case 2: src = We; hi = g_W_hi + DIM * DIM;     lo = g_W_lo + DIM * DIM;     n4 = W4; break;
        default: src = Wo; hi = g_W_hi + 2 * DIM * DIM; lo = g_W_lo + 2 * DIM * DIM; n4 = 2 * W4; break;
    }
    int i = blockIdx.x * blockDim.x + threadIdx.x;
    if (i >= n4) return;
    float4 v = ((const float4*)src)[i];
    __nv_bfloat16 h0 = __float2bfloat16(v.x);
    __nv_bfloat16 h1 = __float2bfloat16(v.y);
    __nv_bfloat16 h2 = __float2bfloat16(v.z);
    __nv_bfloat16 h3 = __float2bfloat16(v.w);
    __nv_bfloat16 l0 = __float2bfloat16(v.x - __bfloat162float(h0));
    __nv_bfloat16 l1 = __float2bfloat16(v.y - __bfloat162float(h1));
    __nv_bfloat16 l2 = __float2bfloat16(v.z - __bfloat162float(h2));
    __nv_bfloat16 l3 = __float2bfloat16(v.w - __bfloat162float(h3));
    ((__nv_bfloat162*)hi)[i * 2 + 0] = __nv_bfloat162(h0, h1);
    ((__nv_bfloat162*)hi)[i * 2 + 1] = __nv_bfloat162(h2, h3);
    ((__nv_bfloat162*)lo)[i * 2 + 0] = __nv_bfloat162(l0, l1);
    ((__nv_bfloat162*)lo)[i * 2 + 1] = __nv_bfloat162(l2, l3);
}

// ---------------------------------------------------------------------------
// MMA / async-copy helpers
// ---------------------------------------------------------------------------
__device__ __forceinline__ void ldsm_x4(uint32_t* r, uint32_t addr)
{
    asm volatile("ldmatrix.sync.aligned.m8n8.x4.shared.b16 {%0,%1,%2,%3}, [%4];"
                 : "=r"(r[0]), "=r"(r[1]), "=r"(r[2]), "=r"(r[3]) : "r"(addr));
}
__device__ __forceinline__ void ldsm_x4_t(uint32_t* r, uint32_t addr)
{
    asm volatile("ldmatrix.sync.aligned.m8n8.x4.trans.shared.b16 {%0,%1,%2,%3}, [%4];"
                 : "=r"(r[0]), "=r"(r[1]), "=r"(r[2]), "=r"(r[3]) : "r"(addr));
}
__device__ __forceinline__ void mma_bf16(float* c, const uint32_t* a, const uint32_t* b)
{
    asm volatile("mma.sync.aligned.m16n8k16.row.col.f32.bf16.bf16.f32 "
                 "{%0,%1,%2,%3}, {%4,%5,%6,%7}, {%8,%9}, {%0,%1,%2,%3};"
                 : "+f"(c[0]), "+f"(c[1]), "+f"(c[2]), "+f"(c[3])
                 : "r"(a[0]), "r"(a[1]), "r"(a[2]), "r"(a[3]), "r"(b[0]), "r"(b[1]));
}
__device__ __forceinline__ void cp16(uint32_t saddr, const void* gaddr)
{
    asm volatile("cp.async.cg.shared.global [%0], [%1], 16;" :: "r"(saddr), "l"(gaddr));
}
__device__ __forceinline__ void cp_commit()
{
    asm volatile("cp.async.commit_group;");
}
template <int N> __device__ __forceinline__ void cp_wait()
{
    asm volatile("cp.async.wait_group %0;" :: "n"(N));
}

// ---------------------------------------------------------------------------
// 3-split bf16 tensor-core GEMM with 3-stage cp.async pipeline.
// C[M,N] = A[M,K] @ W[K,N], M=4096, N=768, K=768.
// BM=128, BN=128, BK=32. 256 threads = 8 warps (2m x 4n), warp tile 64x32.
// Dynamic smem: 3 stages x (Ahi|Alo: 128x40 bf16, Bhi|Blo: 32x136 bf16).
// ---------------------------------------------------------------------------
#define ASTR 40                      // A smem row stride (elements), 80 bytes
#define BSTR 136                     // B smem row stride (elements), 272 bytes
#define A_BYTES (128 * ASTR * 2)     // 10240
#define B_BYTES (32 * BSTR * 2)      // 8704
#define STG_BYTES (2 * A_BYTES + 2 * B_BYTES)  // 37888
#define NSTAGE 3
#define SMEM_TOTAL (NSTAGE * STG_BYTES)        // 113664
#define NIT (DIM / 32)               // 24

template <bool STAGE1>
__device__ __forceinline__ void gemm3_body(
    const __nv_bfloat16* __restrict__ Ahi, const __nv_bfloat16* __restrict__ Alo,
    const __nv_bfloat16* __restrict__ Whi, const __nv_bfloat16* __restrict__ Wlo,
    const float* __restrict__ bias,
    __nv_bfloat16* __restrict__ Ohi, __nv_bfloat16* __restrict__ Olo,
    float* __restrict__ Of)
{
    extern __shared__ char smem[];
    const uint32_t smem_base = (uint32_t)__cvta_generic_to_shared(smem);

    const int tid  = threadIdx.x;
    const int lane = tid & 31;
    const int w    = tid >> 5;
    const int wm   = (w >> 2) * 64;   // warp m offset
    const int wn   = (w & 3) * 32;    // warp n offset
    const int bm   = blockIdx.y * 128;
    const int bn   = blockIdx.x * 128;

    // cp.async chunk mapping (2 chunks of 16B per thread per tile)
    // A: 512 chunks: row = c>>2 (0..127), col = (c&3)*8 elements
    // B: 512 chunks: row = c>>4 (0..31),  col = (c&15)*8 elements
    const int ac0_row = (tid * 2) >> 2,       ac0_col = ((tid * 2) & 3) * 8;
    const int ac1_row = (tid * 2 + 1) >> 2,   ac1_col = ((tid * 2 + 1) & 3) * 8;
    const int bc0_row = tid >> 4,             bc0_col = (tid & 15) * 8;      // c = tid
    const int bc1_row = (tid + 256) >> 4,     bc1_col = (tid & 15) * 8;      // c = tid+256

    auto issue_stage = [&](int stg, int k0) {
        const uint32_t sa_hi = smem_base + stg * STG_BYTES;
        const uint32_t sa_lo = sa_hi + A_BYTES;
        const uint32_t sb_hi = sa_lo + A_BYTES;
        const uint32_t sb_lo = sb_hi + B_BYTES;
        // A hi/lo
        {
            size_t g0 = (size_t)(bm + ac0_row) * DIM + k0 + ac0_col;
            size_t g1 = (size_t)(bm + ac1_row) * DIM + k0 + ac1_col;
            uint32_t s0 = ac0_row * (ASTR * 2) + ac0_col * 2;
            uint32_t s1 = ac1_row * (ASTR * 2) + ac1_col * 2;
            cp16(sa_hi + s0, Ahi + g0);
            cp16(sa_hi + s1, Ahi + g1);
            cp16(sa_lo + s0, Alo + g0);
            cp16(sa_lo + s1, Alo + g1);
        }
        // B hi/lo
        {
            size_t g0 = (size_t)(k0 + bc0_row) * DIM + bn + bc0_col;
            size_t g1 = (size_t)(k0 + bc1_row) * DIM + bn + bc1_col;
            uint32_t s0 = bc0_row * (BSTR * 2) + bc0_col * 2;
            uint32_t s1 = bc1_row * (BSTR * 2) + bc1_col * 2;
            cp16(sb_hi + s0, Whi + g0);
            cp16(sb_hi + s1, Whi + g1);
            cp16(sb_lo + s0, Wlo + g0);
            cp16(sb_lo + s1, Wlo + g1);
        }
        cp_commit();
    };

    float acc[4][4][4];
#pragma unroll
    for (int i = 0; i < 4; i++)
#pragma unroll
        for (int j = 0; j < 4; j++)
#pragma unroll
            for (int k = 0; k < 4; k++) acc[i][j][k] = 0.0f;

    // Prologue: stages 0,1 in flight
    issue_stage(0, 0);
    issue_stage(1, 32);

    for (int it = 0; it < NIT; it++) {
        cp_wait<1>();          // stage it%3 landed (the newest may still fly)
        __syncthreads();

        if (it + 2 < NIT) issue_stage((it + 2) % NSTAGE, (it + 2) * 32);

        const int stg = it % NSTAGE;
        const uint32_t sa_hi = smem_base + stg * STG_BYTES;
        const uint32_t sa_lo = sa_hi + A_BYTES;
        const uint32_t sb_hi = sa_lo + A_BYTES;
        const uint32_t sb_lo = sb_hi + B_BYTES;

#pragma unroll
        for (int kk = 0; kk < 32; kk += 16) {
            uint32_t a_hi[4][4], a_lo[4][4], b_hi[4][2], b_lo[4][2];
#pragma unroll
            for (int mi = 0; mi < 4; mi++) {
                uint32_t off = (wm + mi * 16 + (lane & 15)) * (ASTR * 2)
                             + (kk + (lane >> 4) * 8) * 2;
                ldsm_x4(a_hi[mi], sa_hi + off);
                ldsm_x4(a_lo[mi], sa_lo + off);
            }
#pragma unroll
            for (int ni = 0; ni < 2; ni++) {
                uint32_t off = (kk + (lane & 15)) * (BSTR * 2)
                             + (wn + ni * 16 + (lane >> 4) * 8) * 2;
                uint32_t rh[4], rl[4];
                ldsm_x4_t(rh, sb_hi + off);
                ldsm_x4_t(rl, sb_lo + off);
                b_hi[ni * 2][0] = rh[0]; b_hi[ni * 2][1] = rh[1];
                b_hi[ni * 2 + 1][0] = rh[2]; b_hi[ni * 2 + 1][1] = rh[3];
                b_lo[ni * 2][0] = rl[0]; b_lo[ni * 2][1] = rl[1];
                b_lo[ni * 2 + 1][0] = rl[2]; b_lo[ni * 2 + 1][1] = rl[3];
            }
#pragma unroll
            for (int mi = 0; mi < 4; mi++)
#pragma unroll
                for (int nj = 0; nj < 4; nj++) {
                    mma_bf16(acc[mi][nj], a_hi[mi], b_hi[nj]);
                    mma_bf16(acc[mi][nj], a_hi[mi], b_lo[nj]);
                    mma_bf16(acc[mi][nj], a_lo[mi], b_hi[nj]);
                }
        }
        __syncthreads();       // free stage stg for reuse by issue at it+... 
    }

    // Epilogue. c-frag: c0,c1 -> (row=lane>>2, col=(lane&3)*2+{0,1}); c2,c3 -> row+8.
    const int er = lane >> 2;
    const int ec = (lane & 3) * 2;
#pragma unroll
    for (int mi = 0; mi < 4; mi++) {
#pragma unroll
        for (int nj = 0; nj < 4; nj++) {
            int m0 = bm + wm + mi * 16 + er;
            int n0 = bn + wn + nj * 8 + ec;
            float v0 = acc[mi][nj][0], v1 = acc[mi][nj][1];
            float v2 = acc[mi][nj][2], v3 = acc[mi][nj][3];
            if (STAGE1) {
                float b0 = bias[n0], b1 = bias[n0 + 1];
                v0 = fmaxf(v0 + b0, 0.0f); v1 = fmaxf(v1 + b1, 0.0f);
                v2 = fmaxf(v2 + b0, 0.0f); v3 = fmaxf(v3 + b1, 0.0f);
                __nv_bfloat16 h0 = __float2bfloat16(v0), h1 = __float2bfloat16(v1);
                __nv_bfloat16 h2 = __float2bfloat16(v2), h3 = __float2bfloat16(v3);
                __nv_bfloat16 l0 = __float2bfloat16(v0 - __bfloat162float(h0));
                __nv_bfloat16 l1 = __float2bfloat16(v1 - __bfloat162float(h1));
                __nv_bfloat16 l2 = __float2bfloat16(v2 - __bfloat162float(h2));
                __nv_bfloat16 l3 = __float2bfloat16(v3 - __bfloat162float(h3));
                *(__nv_bfloat162*)&Ohi[(size_t)m0 * DIM + n0] = __nv_bfloat162(h0, h1);
                *(__nv_bfloat162*)&Olo[(size_t)m0 * DIM + n0] = __nv_bfloat162(l0, l1);
                *(__nv_bfloat162*)&Ohi[(size_t)(m0 + 8) * DIM + n0] = __nv_bfloat162(h2, h3);
                *(__nv_bfloat162*)&Olo[(size_t)(m0 + 8) * DIM + n0] = __nv_bfloat162(l2, l3);
            } else {
                *(float2*)&Of[(size_t)m0 * DIM + n0] = make_float2(v0, v1);
                *(float2*)&Of[(size_t)(m0 + 8) * DIM + n0] = make_float2(v2, v3);
            }
        }
    }
}

__global__ __launch_bounds__(256, 2)
void stage1_kernel(const float* __restrict__ bs, const float* __restrict__ be)
{
    if (blockIdx.z == 0)
        gemm3_body<true>(g_h_hi, g_h_lo, g_W_hi, g_W_lo, bs,
                         g_S_hi, g_S_lo, nullptr);
    else
        gemm3_body<true>(g_h_hi, g_h_lo, g_W_hi + DIM * DIM, g_W_lo + DIM * DIM, be,
                         g_E_hi, g_E_lo, nullptr);
}

__global__ __launch_bounds__(256, 2)
void stage2_kernel()
{
    if (blockIdx.z == 0)
        gemm3_body<false>(g_S_hi, g_S_lo, g_W_hi + 2 * DIM * DIM, g_W_lo + 2 * DIM * DIM,
                          nullptr, nullptr, nullptr, g_P);
    else
        gemm3_body<false>(g_E_hi, g_E_lo, g_W_hi + 3 * DIM * DIM, g_W_lo + 3 * DIM * DIM,
                          nullptr, nullptr, nullptr, g_Q);
}

// ---------------------------------------------------------------------------
// Gather-add: out[b,n,:] = P[b, idx_s] + Q[b, idx_e] + bo
// 2 rows per thread (4 independent gathered loads) + streaming stores.
// span_idx is int32 on device (JAX x64 disabled).
// ---------------------------------------------------------------------------
__global__ void gather_add_kernel(const int* __restrict__ span_idx,
                                  const float* __restrict__ bo,
                                  float* __restrict__ out)
{
    const int base = blockIdx.x * 8;
    const int ty = threadIdx.y;                 // 0..3
    const int t  = threadIdx.x;                 // 0..191
    const int r1 = base + ty;
    const int r2 = base + 4 + ty;
    const int b1 = r1 / NSPAN;
    const int b2 = r2 / NSPAN;
    const int is1 = span_idx[r1 * 2], ie1 = span_idx[r1 * 2 + 1];
    const int is2 = span_idx[r2 * 2], ie2 = span_idx[r2 * 2 + 1];

    const float4* p1 = (const float4*)(g_P + (size_t)(b1 * LEN + is1) * DIM);
    const float4* q1 = (const float4*)(g_Q + (size_t)(b1 * LEN + ie1) * DIM);
    const float4* p2 = (const float4*)(g_P + (size_t)(b2 * LEN + is2) * DIM);
    const float4* q2 = (const float4*)(g_Q + (size_t)(b2 * LEN + ie2) * DIM);

    float4 pv1 = p1[t];
    float4 qv1 = q1[t];
    float4 pv2 = p2[t];
    float4 qv2 = q2[t];
    float4 bv  = __ldg(&((const float4*)bo)[t]);

    float4 o1 = make_float4(pv1.x + qv1.x + bv.x, pv1.y + qv1.y + bv.y,
                            pv1.z + qv1.z + bv.z, pv1.w + qv1.w + bv.w);
    float4 o2 = make_float4(pv2.x + qv2.x + bv.x, pv2.y + qv2.y + bv.y,
                            pv2.z + qv2.z + bv.z, pv2.w + qv2.w + bv.w);
    __stcs(&((float4*)(out + (size_t)r1 * DIM))[t], o1);
    __stcs(&((float4*)(out + (size_t)r2 * DIM))[t], o2);
}

extern "C" void kernel_launch(void* const* d_in, const int* in_sizes, int n_in,
                              void* d_out, int out_size)
{
    (void)in_sizes; (void)n_in; (void)out_size;
    const float* h    = (const float*)d_in[0];
    const int*   span = (const int*)d_in[1];
    const float* Ws   = (const float*)d_in[2];
    const float* bs   = (const float*)d_in[3];
    const float* We   = (const float*)d_in[4];
    const float* be   = (const float*)d_in[5];
    const float* Wo   = (const float*)d_in[6];
    const float* bo   = (const float*)d_in[7];
    float* out = (float*)d_out;

    static int smem_set = 0;
    if (!smem_set) {
        cudaFuncSetAttribute(stage1_kernel,
                             cudaFuncAttributeMaxDynamicSharedMemorySize, SMEM_TOTAL);
        cudaFuncSetAttribute(stage2_kernel,
                             cudaFuncAttributeMaxDynamicSharedMemorySize, SMEM_TOTAL);
        smem_set = 1;
    }

    // Split grid covers largest region: h with n4 = 786432 -> 3072 blocks.
    {
        dim3 sgrid(3072, 4);
        split_all_kernel<<<sgrid, 256>>>(h, Ws, We, Wo);
    }

    dim3 gemm_grid(DIM / 128, MROWS / 128, 2);   // (6, 32, 2)
    stage1_kernel<<<gemm_grid, 256, SMEM_TOTAL>>>(bs, be);
    stage2_kernel<<<gemm_grid, 256, SMEM_TOTAL>>>();

    dim3 gblock(192, 4);
    gather_add_kernel<<<(BATCH * NSPAN) / 8, gblock>>>(span, bo, out);
}

// round 8
// speedup vs baseline: 3.4062x; 1.3588x over previous
#include <cuda_runtime.h>
#include <cuda_fp16.h>
#include <cstdint>

#define BATCH 8
#define LEN   512
#define DIM   768
#define MAXW  12
#define NSPAN (LEN * MAXW)          // 6144
#define MROWS (BATCH * LEN)         // 4096

// ---------------------------------------------------------------------------
// Scratch (static device arrays; no allocation allowed)
// ---------------------------------------------------------------------------
__device__ __half g_h[MROWS * DIM];          // fp16(h)
__device__ __half g_S[MROWS * DIM];          // fp16(relu(h@Ws+bs))
__device__ __half g_E[MROWS * DIM];          // fp16(relu(h@We+be))
// Weights [K][N] fp16 hi/lo: [0]=Ws, [1]=We, [2]=Wo_top, [3]=Wo_bot
__device__ __half g_W_hi[4 * DIM * DIM];
__device__ __half g_W_lo[4 * DIM * DIM];
__device__ float g_P[MROWS * DIM];
__device__ float g_Q[MROWS * DIM];

// ---------------------------------------------------------------------------
// fp32 -> fp16 convert for h (single precision term; its quant error is the
// dominant residual ~2e-4 rms, within budget)
// ---------------------------------------------------------------------------
__global__ void hconv_kernel(const float* __restrict__ h)
{
    int i = blockIdx.x * blockDim.x + threadIdx.x;   // < 786432
    float4 v = ((const float4*)h)[i];
    ((__half2*)g_h)[i * 2 + 0] = __floats2half2_rn(v.x, v.y);
    ((__half2*)g_h)[i * 2 + 1] = __floats2half2_rn(v.z, v.w);
}

// ---------------------------------------------------------------------------
// Weight fp32 -> (fp16 hi, fp16 lo) split, layout preserved [K][N].
// blockIdx.y: 0 = Ws, 1 = We, 2 = Wo (both halves, contiguous)
// ---------------------------------------------------------------------------
__global__ void wsplit_kernel(const float* __restrict__ Ws,
                              const float* __restrict__ We,
                              const float* __restrict__ Wo)
{
    const int region = blockIdx.y;
    const int W4 = (DIM * DIM) / 4;   // 147456
    const float* src;
    __half *hi, *lo;
    int n4;
    switch (region) {
        case 0: src = Ws; hi = g_W_hi;                 lo = g_W_lo;                 n4 = W4; break;
        case 1: src = We; hi = g_W_hi + DIM * DIM;     lo = g_W_lo + DIM * DIM;     n4 = W4; break;
        default: src = Wo; hi = g_W_hi + 2 * DIM * DIM; lo = g_W_lo + 2 * DIM * DIM; n4 = 2 * W4; break;
    }
    int i = blockIdx.x * blockDim.x + threadIdx.x;
    if (i >= n4) return;
    float4 v = ((const float4*)src)[i];
    __half h0 = __float2half_rn(v.x), h1 = __float2half_rn(v.y);
    __half h2 = __float2half_rn(v.z), h3 = __float2half_rn(v.w);
    __half l0 = __float2half_rn(v.x - __half2float(h0));
    __half l1 = __float2half_rn(v.y - __half2float(h1));
    __half l2 = __float2half_rn(v.z - __half2float(h2));
    __half l3 = __float2half_rn(v.w - __half2float(h3));
    ((__half2*)hi)[i * 2 + 0] = __halves2half2(h0, h1);
    ((__half2*)hi)[i * 2 + 1] = __halves2half2(h2, h3);
    ((__half2*)lo)[i * 2 + 0] = __halves2half2(l0, l1);
    ((__half2*)lo)[i * 2 + 1] = __halves2half2(l2, l3);
}

// ---------------------------------------------------------------------------
// MMA / async-copy helpers (fp16)
// ---------------------------------------------------------------------------
__device__ __forceinline__ void ldsm_x4(uint32_t* r, uint32_t addr)
{
    asm volatile("ldmatrix.sync.aligned.m8n8.x4.shared.b16 {%0,%1,%2,%3}, [%4];"
                 : "=r"(r[0]), "=r"(r[1]), "=r"(r[2]), "=r"(r[3]) : "r"(addr));
}
__device__ __forceinline__ void ldsm_x4_t(uint32_t* r, uint32_t addr)
{
    asm volatile("ldmatrix.sync.aligned.m8n8.x4.trans.shared.b16 {%0,%1,%2,%3}, [%4];"
                 : "=r"(r[0]), "=r"(r[1]), "=r"(r[2]), "=r"(r[3]) : "r"(addr));
}
__device__ __forceinline__ void mma_f16(float* c, const uint32_t* a, const uint32_t* b)
{
    asm volatile("mma.sync.aligned.m16n8k16.row.col.f32.f16.f16.f32 "
                 "{%0,%1,%2,%3}, {%4,%5,%6,%7}, {%8,%9}, {%0,%1,%2,%3};"
                 : "+f"(c[0]), "+f"(c[1]), "+f"(c[2]), "+f"(c[3])
                 : "r"(a[0]), "r"(a[1]), "r"(a[2]), "r"(a[3]), "r"(b[0]), "r"(b[1]));
}
__device__ __forceinline__ void cp16(uint32_t saddr, const void* gaddr)
{
    asm volatile("cp.async.cg.shared.global [%0], [%1], 16;" :: "r"(saddr), "l"(gaddr));
}
__device__ __forceinline__ void cp_commit() { asm volatile("cp.async.commit_group;"); }
template <int N> __device__ __forceinline__ void cp_wait()
{
    asm volatile("cp.async.wait_group %0;" :: "n"(N));
}

// ---------------------------------------------------------------------------
// 2-term fp16 tensor-core GEMM with 3-stage cp.async pipeline.
// C[M,N] = A[M,K] @ (W_hi + W_lo)[K,N], M=4096, N=768, K=768.
// BM=128, BN=128, BK=32. 256 threads = 8 warps (2m x 4n), warp tile 64x32.
// Dynamic smem: 3 stages x (A: 128x40 fp16, Bhi|Blo: 32x136 fp16 each).
// ---------------------------------------------------------------------------
#define ASTR 40                      // A smem row stride (elems)
#define BSTR 136                     // B smem row stride (elems)
#define A_BYTES (128 * ASTR * 2)     // 10240
#define B_BYTES (32 * BSTR * 2)      // 8704
#define STG_BYTES (A_BYTES + 2 * B_BYTES)   // 27648
#define NSTAGE 3
#define SMEM_TOTAL (NSTAGE * STG_BYTES)     // 82944
#define NIT (DIM / 32)               // 24

template <bool STAGE1>
__device__ __forceinline__ void gemm2_body(
    const __half* __restrict__ A,
    const __half* __restrict__ Whi, const __half* __restrict__ Wlo,
    const float* __restrict__ bias,
    __half* __restrict__ Oh,
    float* __restrict__ Of)
{
    extern __shared__ char smem[];
    const uint32_t smem_base = (uint32_t)__cvta_generic_to_shared(smem);

    const int tid  = threadIdx.x;
    const int lane = tid & 31;
    const int w    = tid >> 5;
    const int wm   = (w >> 2) * 64;   // warp m offset
    const int wn   = (w & 3) * 32;    // warp n offset
    const int bm   = blockIdx.y * 128;
    const int bn   = blockIdx.x * 128;

    // A: 512 chunks of 16B: row = c>>2 (0..127), col = (c&3)*8 elems; 2/thread
    const int ac0_row = (tid * 2) >> 2,     ac0_col = ((tid * 2) & 3) * 8;
    const int ac1_row = (tid * 2 + 1) >> 2, ac1_col = ((tid * 2 + 1) & 3) * 8;
    // B: 512 chunks: row = c>>4 (0..31), col = (c&15)*8; 2/thread per split
    const int bc0_row = tid >> 4,           bc0_col = (tid & 15) * 8;
    const int bc1_row = (tid + 256) >> 4,   bc1_col = (tid & 15) * 8;

    auto issue_stage = [&](int stg, int k0) {
        const uint32_t sa   = smem_base + stg * STG_BYTES;
        const uint32_t sb_h = sa + A_BYTES;
        const uint32_t sb_l = sb_h + B_BYTES;
        {
            size_t g0 = (size_t)(bm + ac0_row) * DIM + k0 + ac0_col;
            size_t g1 = (size_t)(bm + ac1_row) * DIM + k0 + ac1_col;
            cp16(sa + ac0_row * (ASTR * 2) + ac0_col * 2, A + g0);
            cp16(sa + ac1_row * (ASTR * 2) + ac1_col * 2, A + g1);
        }
        {
            size_t g0 = (size_t)(k0 + bc0_row) * DIM + bn + bc0_col;
            size_t g1 = (size_t)(k0 + bc1_row) * DIM + bn + bc1_col;
            uint32_t s0 = bc0_row * (BSTR * 2) + bc0_col * 2;
            uint32_t s1 = bc1_row * (BSTR * 2) + bc1_col * 2;
            cp16(sb_h + s0, Whi + g0);
            cp16(sb_h + s1, Whi + g1);
            cp16(sb_l + s0, Wlo + g0);
            cp16(sb_l + s1, Wlo + g1);
        }
        cp_commit();
    };

    float acc[4][4][4];
#pragma unroll
    for (int i = 0; i < 4; i++)
#pragma unroll
        for (int j = 0; j < 4; j++)
#pragma unroll
            for (int k = 0; k < 4; k++) acc[i][j][k] = 0.0f;

    issue_stage(0, 0);
    issue_stage(1, 32);

    for (int it = 0; it < NIT; it++) {
        cp_wait<1>();
        __syncthreads();

        if (it + 2 < NIT) issue_stage((it + 2) % NSTAGE, (it + 2) * 32);

        const int stg = it % NSTAGE;
        const uint32_t sa   = smem_base + stg * STG_BYTES;
        const uint32_t sb_h = sa + A_BYTES;
        const uint32_t sb_l = sb_h + B_BYTES;

#pragma unroll
        for (int kk = 0; kk < 32; kk += 16) {
            uint32_t af[4][4], b_hi[4][2], b_lo[4][2];
#pragma unroll
            for (int mi = 0; mi < 4; mi++) {
                uint32_t off = (wm + mi * 16 + (lane & 15)) * (ASTR * 2)
                             + (kk + (lane >> 4) * 8) * 2;
                ldsm_x4(af[mi], sa + off);
            }
#pragma unroll
            for (int ni = 0; ni < 2; ni++) {
                uint32_t off = (kk + (lane & 15)) * (BSTR * 2)
                             + (wn + ni * 16 + (lane >> 4) * 8) * 2;
                uint32_t rh[4], rl[4];
                ldsm_x4_t(rh, sb_h + off);
                ldsm_x4_t(rl, sb_l + off);
                b_hi[ni * 2][0] = rh[0]; b_hi[ni * 2][1] = rh[1];
                b_hi[ni * 2 + 1][0] = rh[2]; b_hi[ni * 2 + 1][1] = rh[3];
                b_lo[ni * 2][0] = rl[0]; b_lo[ni * 2][1] = rl[1];
                b_lo[ni * 2 + 1][0] = rl[2]; b_lo[ni * 2 + 1][1] = rl[3];
            }
#pragma unroll
            for (int mi = 0; mi < 4; mi++)
#pragma unroll
                for (int nj = 0; nj < 4; nj++) {
                    mma_f16(acc[mi][nj], af[mi], b_hi[nj]);
                    mma_f16(acc[mi][nj], af[mi], b_lo[nj]);
                }
        }
        __syncthreads();
    }

    // Epilogue. c-frag: c0,c1 -> (row=lane>>2, col=(lane&3)*2+{0,1}); c2,c3 -> row+8.
    const int er = lane >> 2;
    const int ec = (lane & 3) * 2;
#pragma unroll
    for (int mi = 0; mi < 4; mi++) {
#pragma unroll
        for (int nj = 0; nj < 4; nj++) {
            int m0 = bm + wm + mi * 16 + er;
            int n0 = bn + wn + nj * 8 + ec;
            float v0 = acc[mi][nj][0], v1 = acc[mi][nj][1];
            float v2 = acc[mi][nj][2], v3 = acc[mi][nj][3];
            if (STAGE1) {
                float b0 = bias[n0], b1 = bias[n0 + 1];
                v0 = fmaxf(v0 + b0, 0.0f); v1 = fmaxf(v1 + b1, 0.0f);
                v2 = fmaxf(v2 + b0, 0.0f); v3 = fmaxf(v3 + b1, 0.0f);
                *(__half2*)&Oh[(size_t)m0 * DIM + n0]       = __floats2half2_rn(v0, v1);
                *(__half2*)&Oh[(size_t)(m0 + 8) * DIM + n0] = __floats2half2_rn(v2, v3);
            } else {
                *(float2*)&Of[(size_t)m0 * DIM + n0]       = make_float2(v0, v1);
                *(float2*)&Of[(size_t)(m0 + 8) * DIM + n0] = make_float2(v2, v3);
            }
        }
    }
}

__global__ __launch_bounds__(256, 2)
void stage1_kernel(const float* __restrict__ bs, const float* __restrict__ be)
{
    if (blockIdx.z == 0)
        gemm2_body<true>(g_h, g_W_hi, g_W_lo, bs, g_S, nullptr);
    else
        gemm2_body<true>(g_h, g_W_hi + DIM * DIM, g_W_lo + DIM * DIM, be, g_E, nullptr);
}

__global__ __launch_bounds__(256, 2)
void stage2_kernel()
{
    if (blockIdx.z == 0)
        gemm2_body<false>(g_S, g_W_hi + 2 * DIM * DIM, g_W_lo + 2 * DIM * DIM,
                          nullptr, nullptr, g_P);
    else
        gemm2_body<false>(g_E, g_W_hi + 3 * DIM * DIM, g_W_lo + 3 * DIM * DIM,
                          nullptr, nullptr, g_Q);
}

// ---------------------------------------------------------------------------
// Gather-add: out[b,n,:] = P[b, idx_s] + Q[b, idx_e] + bo   (span_idx int32)
// 2 rows/thread for MLP, streaming stores for the write-once output.
// ---------------------------------------------------------------------------
__global__ void gather_add_kernel(const int* __restrict__ span_idx,
                                  const float* __restrict__ bo,
                                  float* __restrict__ out)
{
    const int base = blockIdx.x * 8;
    const int ty = threadIdx.y;
    const int t  = threadIdx.x;                 // 0..191
    const int r1 = base + ty;
    const int r2 = base + 4 + ty;
    const int b1 = r1 / NSPAN;
    const int b2 = r2 / NSPAN;
    const int is1 = span_idx[r1 * 2], ie1 = span_idx[r1 * 2 + 1];
    const int is2 = span_idx[r2 * 2], ie2 = span_idx[r2 * 2 + 1];

    const float4* p1 = (const float4*)(g_P + (size_t)(b1 * LEN + is1) * DIM);
    const float4* q1 = (const float4*)(g_Q + (size_t)(b1 * LEN + ie1) * DIM);
    const float4* p2 = (const float4*)(g_P + (size_t)(b2 * LEN + is2) * DIM);
    const float4* q2 = (const float4*)(g_Q + (size_t)(b2 * LEN + ie2) * DIM);

    float4 pv1 = p1[t];
    float4 qv1 = q1[t];
    float4 pv2 = p2[t];
    float4 qv2 = q2[t];
    float4 bv  = __ldg(&((const float4*)bo)[t]);

    float4 o1 = make_float4(pv1.x + qv1.x + bv.x, pv1.y + qv1.y + bv.y,
                            pv1.z + qv1.z + bv.z, pv1.w + qv1.w + bv.w);
    float4 o2 = make_float4(pv2.x + qv2.x + bv.x, pv2.y + qv2.y + bv.y,
                            pv2.z + qv2.z + bv.z, pv2.w + qv2.w + bv.w);
    __stcs(&((float4*)(out + (size_t)r1 * DIM))[t], o1);
    __stcs(&((float4*)(out + (size_t)r2 * DIM))[t], o2);
}

extern "C" void kernel_launch(void* const* d_in, const int* in_sizes, int n_in,
                              void* d_out, int out_size)
{
    (void)in_sizes; (void)n_in; (void)out_size;
    const float* h    = (const float*)d_in[0];
    const int*   span = (const int*)d_in[1];
    const float* Ws   = (const float*)d_in[2];
    const float* bs   = (const float*)d_in[3];
    const float* We   = (const float*)d_in[4];
    const float* be   = (const float*)d_in[5];
    const float* Wo   = (const float*)d_in[6];
    const float* bo   = (const float*)d_in[7];
    float* out = (float*)d_out;

    static int smem_set = 0;
    if (!smem_set) {
        cudaFuncSetAttribute(stage1_kernel,
                             cudaFuncAttributeMaxDynamicSharedMemorySize, SMEM_TOTAL);
        cudaFuncSetAttribute(stage2_kernel,
                             cudaFuncAttributeMaxDynamicSharedMemorySize, SMEM_TOTAL);
        smem_set = 1;
    }

    hconv_kernel<<<3072, 256>>>(h);                    // 786432 float4s
    wsplit_kernel<<<dim3(1152, 3), 256>>>(Ws, We, Wo); // max region n4 = 294912

    dim3 gemm_grid(DIM / 128, MROWS / 128, 2);         // (6, 32, 2)
    stage1_kernel<<<gemm_grid, 256, SMEM_TOTAL>>>(bs, be);
    stage2_kernel<<<gemm_grid, 256, SMEM_TOTAL>>>();

    dim3 gblock(192, 4);
    gather_add_kernel<<<(BATCH * NSPAN) / 8, gblock>>>(span, bo, out);
}

// round 9
// speedup vs baseline: 4.7942x; 1.4075x over previous
#include <cuda_runtime.h>
#include <cuda_fp16.h>
#include <cstdint>

#define BATCH 8
#define LEN   512
#define DIM   768
#define MAXW  12
#define NSPAN (LEN * MAXW)          // 6144
#define MROWS (BATCH * LEN)         // 4096

// ---------------------------------------------------------------------------
// Scratch (static device arrays; no allocation allowed)
// ---------------------------------------------------------------------------
__device__ __half g_h[MROWS * DIM];          // fp16(h)
__device__ __half g_S[MROWS * DIM];          // fp16(relu(h@Ws+bs))
__device__ __half g_E[MROWS * DIM];          // fp16(relu(h@We+be))
// Weights [K][N] fp16: [0]=Ws, [1]=We, [2]=Wo_top, [3]=Wo_bot
__device__ __half g_W[4 * DIM * DIM];
__device__ float g_P[MROWS * DIM];
__device__ float g_Q[MROWS * DIM];

// ---------------------------------------------------------------------------
// fp32 -> fp16 convert for h
// ---------------------------------------------------------------------------
__global__ void hconv_kernel(const float* __restrict__ h)
{
    int i = blockIdx.x * blockDim.x + threadIdx.x;   // < 786432
    float4 v = ((const float4*)h)[i];
    ((__half2*)g_h)[i * 2 + 0] = __floats2half2_rn(v.x, v.y);
    ((__half2*)g_h)[i * 2 + 1] = __floats2half2_rn(v.z, v.w);
}

// ---------------------------------------------------------------------------
// Weight fp32 -> fp16, layout preserved [K][N].
// blockIdx.y: 0 = Ws, 1 = We, 2 = Wo (both halves contiguous)
// ---------------------------------------------------------------------------
__global__ void wconv_kernel(const float* __restrict__ Ws,
                             const float* __restrict__ We,
                             const float* __restrict__ Wo)
{
    const int region = blockIdx.y;
    const int W4 = (DIM * DIM) / 4;   // 147456
    const float* src;
    __half* dst;
    int n4;
    switch (region) {
        case 0: src = Ws; dst = g_W;                 n4 = W4; break;
        case 1: src = We; dst = g_W + DIM * DIM;     n4 = W4; break;
        default: src = Wo; dst = g_W + 2 * DIM * DIM; n4 = 2 * W4; break;
    }
    int i = blockIdx.x * blockDim.x + threadIdx.x;
    if (i >= n4) return;
    float4 v = ((const float4*)src)[i];
    ((__half2*)dst)[i * 2 + 0] = __floats2half2_rn(v.x, v.y);
    ((__half2*)dst)[i * 2 + 1] = __floats2half2_rn(v.z, v.w);
}

// ---------------------------------------------------------------------------
// MMA / async-copy helpers (fp16)
// ---------------------------------------------------------------------------
__device__ __forceinline__ void ldsm_x4(uint32_t* r, uint32_t addr)
{
    asm volatile("ldmatrix.sync.aligned.m8n8.x4.shared.b16 {%0,%1,%2,%3}, [%4];"
                 : "=r"(r[0]), "=r"(r[1]), "=r"(r[2]), "=r"(r[3]) : "r"(addr));
}
__device__ __forceinline__ void ldsm_x4_t(uint32_t* r, uint32_t addr)
{
    asm volatile("ldmatrix.sync.aligned.m8n8.x4.trans.shared.b16 {%0,%1,%2,%3}, [%4];"
                 : "=r"(r[0]), "=r"(r[1]), "=r"(r[2]), "=r"(r[3]) : "r"(addr));
}
__device__ __forceinline__ void mma_f16(float* c, const uint32_t* a, const uint32_t* b)
{
    asm volatile("mma.sync.aligned.m16n8k16.row.col.f32.f16.f16.f32 "
                 "{%0,%1,%2,%3}, {%4,%5,%6,%7}, {%8,%9}, {%0,%1,%2,%3};"
                 : "+f"(c[0]), "+f"(c[1]), "+f"(c[2]), "+f"(c[3])
                 : "r"(a[0]), "r"(a[1]), "r"(a[2]), "r"(a[3]), "r"(b[0]), "r"(b[1]));
}
__device__ __forceinline__ void cp16(uint32_t saddr, const void* gaddr)
{
    asm volatile("cp.async.cg.shared.global [%0], [%1], 16;" :: "r"(saddr), "l"(gaddr));
}
__device__ __forceinline__ void cp_commit() { asm volatile("cp.async.commit_group;"); }
template <int N> __device__ __forceinline__ void cp_wait()
{
    asm volatile("cp.async.wait_group %0;" :: "n"(N));
}

// ---------------------------------------------------------------------------
// Single-term fp16 tensor-core GEMM with 4-stage cp.async pipeline.
// C[M,N] = A[M,K] @ W[K,N], M=4096, N=768, K=768.
// BM=128, BN=128, BK=32. 256 threads = 8 warps (2m x 4n), warp tile 64x32.
// Dynamic smem: 4 stages x (A: 128x40 fp16, B: 32x136 fp16).
// ---------------------------------------------------------------------------
#define ASTR 40                      // A smem row stride (elems)
#define BSTR 136                     // B smem row stride (elems)
#define A_BYTES (128 * ASTR * 2)     // 10240
#define B_BYTES (32 * BSTR * 2)      // 8704
#define STG_BYTES (A_BYTES + B_BYTES)       // 18944
#define NSTAGE 4
#define SMEM_TOTAL (NSTAGE * STG_BYTES)     // 75776
#define NIT (DIM / 32)               // 24

template <bool STAGE1>
__device__ __forceinline__ void gemm_body(
    const __half* __restrict__ A,
    const __half* __restrict__ W,
    const float* __restrict__ bias,
    __half* __restrict__ Oh,
    float* __restrict__ Of)
{
    extern __shared__ char smem[];
    const uint32_t smem_base = (uint32_t)__cvta_generic_to_shared(smem);

    const int tid  = threadIdx.x;
    const int lane = tid & 31;
    const int w    = tid >> 5;
    const int wm   = (w >> 2) * 64;   // warp m offset
    const int wn   = (w & 3) * 32;    // warp n offset
    const int bm   = blockIdx.y * 128;
    const int bn   = blockIdx.x * 128;

    // A: 512 chunks of 16B: row = c>>2 (0..127), col = (c&3)*8 elems; 2/thread
    const int ac0_row = (tid * 2) >> 2,     ac0_col = ((tid * 2) & 3) * 8;
    const int ac1_row = (tid * 2 + 1) >> 2, ac1_col = ((tid * 2 + 1) & 3) * 8;
    // B: 512 chunks: row = c>>4 (0..31), col = (c&15)*8; 2/thread
    const int bc0_row = tid >> 4,           bc0_col = (tid & 15) * 8;
    const int bc1_row = (tid + 256) >> 4,   bc1_col = (tid & 15) * 8;

    auto issue_stage = [&](int stg, int k0) {
        const uint32_t sa = smem_base + stg * STG_BYTES;
        const uint32_t sb = sa + A_BYTES;
        {
            size_t g0 = (size_t)(bm + ac0_row) * DIM + k0 + ac0_col;
            size_t g1 = (size_t)(bm + ac1_row) * DIM + k0 + ac1_col;
            cp16(sa + ac0_row * (ASTR * 2) + ac0_col * 2, A + g0);
            cp16(sa + ac1_row * (ASTR * 2) + ac1_col * 2, A + g1);
        }
        {
            size_t g0 = (size_t)(k0 + bc0_row) * DIM + bn + bc0_col;
            size_t g1 = (size_t)(k0 + bc1_row) * DIM + bn + bc1_col;
            cp16(sb + bc0_row * (BSTR * 2) + bc0_col * 2, W + g0);
            cp16(sb + bc1_row * (BSTR * 2) + bc1_col * 2, W + g1);
        }
        cp_commit();
    };

    float acc[4][4][4];
#pragma unroll
    for (int i = 0; i < 4; i++)
#pragma unroll
        for (int j = 0; j < 4; j++)
#pragma unroll
            for (int k = 0; k < 4; k++) acc[i][j][k] = 0.0f;

    issue_stage(0, 0);
    issue_stage(1, 32);
    issue_stage(2, 64);

    for (int it = 0; it < NIT; it++) {
        cp_wait<2>();          // stage it landed (2 newer may fly)
        __syncthreads();

        if (it + 3 < NIT) issue_stage((it + 3) % NSTAGE, (it + 3) * 32);

        const int stg = it % NSTAGE;
        const uint32_t sa = smem_base + stg * STG_BYTES;
        const uint32_t sb = sa + A_BYTES;

#pragma unroll
        for (int kk = 0; kk < 32; kk += 16) {
            uint32_t af[4][4], bf[4][2];
#pragma unroll
            for (int mi = 0; mi < 4; mi++) {
                uint32_t off = (wm + mi * 16 + (lane & 15)) * (ASTR * 2)
                             + (kk + (lane >> 4) * 8) * 2;
                ldsm_x4(af[mi], sa + off);
            }
#pragma unroll
            for (int ni = 0; ni < 2; ni++) {
                uint32_t off = (kk + (lane & 15)) * (BSTR * 2)
                             + (wn + ni * 16 + (lane >> 4) * 8) * 2;
                uint32_t rb[4];
                ldsm_x4_t(rb, sb + off);
                bf[ni * 2][0] = rb[0]; bf[ni * 2][1] = rb[1];
                bf[ni * 2 + 1][0] = rb[2]; bf[ni * 2 + 1][1] = rb[3];
            }
#pragma unroll
            for (int mi = 0; mi < 4; mi++)
#pragma unroll
                for (int nj = 0; nj < 4; nj++)
                    mma_f16(acc[mi][nj], af[mi], bf[nj]);
        }
        __syncthreads();
    }

    // Epilogue. c-frag: c0,c1 -> (row=lane>>2, col=(lane&3)*2+{0,1}); c2,c3 -> row+8.
    const int er = lane >> 2;
    const int ec = (lane & 3) * 2;
#pragma unroll
    for (int mi = 0; mi < 4; mi++) {
#pragma unroll
        for (int nj = 0; nj < 4; nj++) {
            int m0 = bm + wm + mi * 16 + er;
            int n0 = bn + wn + nj * 8 + ec;
            float v0 = acc[mi][nj][0], v1 = acc[mi][nj][1];
            float v2 = acc[mi][nj][2], v3 = acc[mi][nj][3];
            if (STAGE1) {
                float b0 = bias[n0], b1 = bias[n0 + 1];
                v0 = fmaxf(v0 + b0, 0.0f); v1 = fmaxf(v1 + b1, 0.0f);
                v2 = fmaxf(v2 + b0, 0.0f); v3 = fmaxf(v3 + b1, 0.0f);
                *(__half2*)&Oh[(size_t)m0 * DIM + n0]       = __floats2half2_rn(v0, v1);
                *(__half2*)&Oh[(size_t)(m0 + 8) * DIM + n0] = __floats2half2_rn(v2, v3);
            } else {
                *(float2*)&Of[(size_t)m0 * DIM + n0]       = make_float2(v0, v1);
                *(float2*)&Of[(size_t)(m0 + 8) * DIM + n0] = make_float2(v2, v3);
            }
        }
    }
}

__global__ __launch_bounds__(256, 2)
void stage1_kernel(const float* __restrict__ bs, const float* __restrict__ be)
{
    if (blockIdx.z == 0)
        gemm_body<true>(g_h, g_W, bs, g_S, nullptr);
    else
        gemm_body<true>(g_h, g_W + DIM * DIM, be, g_E, nullptr);
}

__global__ __launch_bounds__(256, 2)
void stage2_kernel()
{
    if (blockIdx.z == 0)
        gemm_body<false>(g_S, g_W + 2 * DIM * DIM, nullptr, nullptr, g_P);
    else
        gemm_body<false>(g_E, g_W + 3 * DIM * DIM, nullptr, nullptr, g_Q);
}

// ---------------------------------------------------------------------------
// Gather-add: out[b,n,:] = P[b, idx_s] + Q[b, idx_e] + bo   (span_idx int32)
// 4 rows per thread (8 independent gathered loads), streaming stores.
// ---------------------------------------------------------------------------
__global__ void gather_add_kernel(const int* __restrict__ span_idx,
                                  const float* __restrict__ bo,
                                  float* __restrict__ out)
{
    const int base = blockIdx.x * 16;
    const int ty = threadIdx.y;                 // 0..3
    const int t  = threadIdx.x;                 // 0..191
    float4 bv = __ldg(&((const float4*)bo)[t]);

    int   rows[4];
    const float4* pp[4];
    const float4* qq[4];
#pragma unroll
    for (int j = 0; j < 4; j++) {
        int r = base + j * 4 + ty;
        int b = r / NSPAN;
        int is = span_idx[r * 2], ie = span_idx[r * 2 + 1];
        rows[j] = r;
        pp[j] = (const float4*)(g_P + (size_t)(b * LEN + is) * DIM);
        qq[j] = (const float4*)(g_Q + (size_t)(b * LEN + ie) * DIM);
    }
    float4 pv[4], qv[4];
#pragma unroll
    for (int j = 0; j < 4; j++) pv[j] = pp[j][t];
#pragma unroll
    for (int j = 0; j < 4; j++) qv[j] = qq[j][t];
#pragma unroll
    for (int j = 0; j < 4; j++) {
        float4 o = make_float4(pv[j].x + qv[j].x + bv.x,
                               pv[j].y + qv[j].y + bv.y,
                               pv[j].z + qv[j].z + bv.z,
                               pv[j].w + qv[j].w + bv.w);
        __stcs(&((float4*)(out + (size_t)rows[j] * DIM))[t], o);
    }
}

extern "C" void kernel_launch(void* const* d_in, const int* in_sizes, int n_in,
                              void* d_out, int out_size)
{
    (void)in_sizes; (void)n_in; (void)out_size;
    const float* h    = (const float*)d_in[0];
    const int*   span = (const int*)d_in[1];
    const float* Ws   = (const float*)d_in[2];
    const float* bs   = (const float*)d_in[3];
    const float* We   = (const float*)d_in[4];
    const float* be   = (const float*)d_in[5];
    const float* Wo   = (const float*)d_in[6];
    const float* bo   = (const float*)d_in[7];
    float* out = (float*)d_out;

    static int smem_set = 0;
    if (!smem_set) {
        cudaFuncSetAttribute(stage1_kernel,
                             cudaFuncAttributeMaxDynamicSharedMemorySize, SMEM_TOTAL);
        cudaFuncSetAttribute(stage2_kernel,
                             cudaFuncAttributeMaxDynamicSharedMemorySize, SMEM_TOTAL);
        smem_set = 1;
    }

    hconv_kernel<<<3072, 256>>>(h);                    // 786432 float4s
    wconv_kernel<<<dim3(1152, 3), 256>>>(Ws, We, Wo);  // max region n4 = 294912

    dim3 gemm_grid(DIM / 128, MROWS / 128, 2);         // (6, 32, 2)
    stage1_kernel<<<gemm_grid, 256, SMEM_TOTAL>>>(bs, be);
    stage2_kernel<<<gemm_grid, 256, SMEM_TOTAL>>>();

    dim3 gblock(192, 4);
    gather_add_kernel<<<(BATCH * NSPAN) / 16, gblock>>>(span, bo, out);
}

// round 10
// speedup vs baseline: 5.1097x; 1.0658x over previous
#include <cuda_runtime.h>
#include <cuda_fp16.h>
#include <cstdint>

#define BATCH 8
#define LEN   512
#define DIM   768
#define MAXW  12
#define NSPAN (LEN * MAXW)          // 6144
#define MROWS (BATCH * LEN)         // 4096

// ---------------------------------------------------------------------------
// Scratch (static device arrays; no allocation allowed)
// ---------------------------------------------------------------------------
__device__ __half g_h[MROWS * DIM];          // fp16(h)
__device__ __half g_S[MROWS * DIM];          // fp16(relu(h@Ws+bs))
__device__ __half g_E[MROWS * DIM];          // fp16(relu(h@We+be))
// Weights [K][N] fp16: [0]=Ws, [1]=We, [2]=Wo_top, [3]=Wo_bot
__device__ __half g_W[4 * DIM * DIM];
__device__ float g_P[MROWS * DIM];
__device__ float g_Q[MROWS * DIM];

// ---------------------------------------------------------------------------
// fp32 -> fp16 convert for h
// ---------------------------------------------------------------------------
__global__ void hconv_kernel(const float* __restrict__ h)
{
    int i = blockIdx.x * blockDim.x + threadIdx.x;   // < 786432
    float4 v = ((const float4*)h)[i];
    ((__half2*)g_h)[i * 2 + 0] = __floats2half2_rn(v.x, v.y);
    ((__half2*)g_h)[i * 2 + 1] = __floats2half2_rn(v.z, v.w);
}

// ---------------------------------------------------------------------------
// Weight fp32 -> fp16, layout preserved [K][N].
// blockIdx.y: 0 = Ws, 1 = We, 2 = Wo (both halves contiguous)
// ---------------------------------------------------------------------------
__global__ void wconv_kernel(const float* __restrict__ Ws,
                             const float* __restrict__ We,
                             const float* __restrict__ Wo)
{
    const int region = blockIdx.y;
    const int W4 = (DIM * DIM) / 4;   // 147456
    const float* src;
    __half* dst;
    int n4;
    switch (region) {
        case 0: src = Ws; dst = g_W;                 n4 = W4; break;
        case 1: src = We; dst = g_W + DIM * DIM;     n4 = W4; break;
        default: src = Wo; dst = g_W + 2 * DIM * DIM; n4 = 2 * W4; break;
    }
    int i = blockIdx.x * blockDim.x + threadIdx.x;
    if (i >= n4) return;
    float4 v = ((const float4*)src)[i];
    ((__half2*)dst)[i * 2 + 0] = __floats2half2_rn(v.x, v.y);
    ((__half2*)dst)[i * 2 + 1] = __floats2half2_rn(v.z, v.w);
}

// ---------------------------------------------------------------------------
// MMA / async-copy helpers (fp16)
// ---------------------------------------------------------------------------
__device__ __forceinline__ void ldsm_x4(uint32_t* r, uint32_t addr)
{
    asm volatile("ldmatrix.sync.aligned.m8n8.x4.shared.b16 {%0,%1,%2,%3}, [%4];"
                 : "=r"(r[0]), "=r"(r[1]), "=r"(r[2]), "=r"(r[3]) : "r"(addr));
}
__device__ __forceinline__ void ldsm_x4_t(uint32_t* r, uint32_t addr)
{
    asm volatile("ldmatrix.sync.aligned.m8n8.x4.trans.shared.b16 {%0,%1,%2,%3}, [%4];"
                 : "=r"(r[0]), "=r"(r[1]), "=r"(r[2]), "=r"(r[3]) : "r"(addr));
}
__device__ __forceinline__ void mma_f16(float* c, const uint32_t* a, const uint32_t* b)
{
    asm volatile("mma.sync.aligned.m16n8k16.row.col.f32.f16.f16.f32 "
                 "{%0,%1,%2,%3}, {%4,%5,%6,%7}, {%8,%9}, {%0,%1,%2,%3};"
                 : "+f"(c[0]), "+f"(c[1]), "+f"(c[2]), "+f"(c[3])
                 : "r"(a[0]), "r"(a[1]), "r"(a[2]), "r"(a[3]), "r"(b[0]), "r"(b[1]));
}
__device__ __forceinline__ void cp16(uint32_t saddr, const void* gaddr)
{
    asm volatile("cp.async.cg.shared.global [%0], [%1], 16;" :: "r"(saddr), "l"(gaddr));
}
__device__ __forceinline__ void cp_commit() { asm volatile("cp.async.commit_group;"); }
template <int N> __device__ __forceinline__ void cp_wait()
{
    asm volatile("cp.async.wait_group %0;" :: "n"(N));
}

// ---------------------------------------------------------------------------
// Single-term fp16 tensor-core GEMM, 4-stage cp.async pipeline.
// C[M,N] = A[M,K] @ W[K,N], M=4096, N=768, K=768.
// BM=128, BN=128, BK=32. 128 threads = 4 warps (2m x 2n), warp tile 64x64.
// One __syncthreads per iter (issue slot (it+3)%4 == (it-1)%4, freed by barrier).
// ---------------------------------------------------------------------------
#define ASTR 40                      // A smem row stride (elems)
#define BSTR 136                     // B smem row stride (elems)
#define A_BYTES (128 * ASTR * 2)     // 10240
#define B_BYTES (32 * BSTR * 2)      // 8704
#define STG_BYTES (A_BYTES + B_BYTES)       // 18944
#define NSTAGE 4
#define SMEM_TOTAL (NSTAGE * STG_BYTES)     // 75776
#define NIT (DIM / 32)               // 24

template <bool STAGE1>
__device__ __forceinline__ void gemm_body(
    const __half* __restrict__ A,
    const __half* __restrict__ W,
    const float* __restrict__ bias,
    __half* __restrict__ Oh,
    float* __restrict__ Of)
{
    extern __shared__ char smem[];
    const uint32_t smem_base = (uint32_t)__cvta_generic_to_shared(smem);

    const int tid  = threadIdx.x;          // 0..127
    const int lane = tid & 31;
    const int w    = tid >> 5;             // 0..3
    const int wm   = (w >> 1) * 64;        // warp m offset (0 or 64)
    const int wn   = (w & 1) * 64;         // warp n offset (0 or 64)
    const int bm   = blockIdx.y * 128;
    const int bn   = blockIdx.x * 128;

    // A: 512 16B-chunks, 4/thread: c = tid + i*128, row = c>>2, col = (c&3)*8
    // B: 512 16B-chunks, 4/thread: c = tid + i*128, row = c>>4, col = (c&15)*8
    auto issue_stage = [&](int stg, int k0) {
        const uint32_t sa = smem_base + stg * STG_BYTES;
        const uint32_t sb = sa + A_BYTES;
#pragma unroll
        for (int i = 0; i < 4; i++) {
            int c = tid + i * 128;
            int ar = c >> 2, ac = (c & 3) * 8;
            cp16(sa + ar * (ASTR * 2) + ac * 2,
                 A + (size_t)(bm + ar) * DIM + k0 + ac);
        }
#pragma unroll
        for (int i = 0; i < 4; i++) {
            int c = tid + i * 128;
            int br = c >> 4, bc2 = (c & 15) * 8;
            cp16(sb + br * (BSTR * 2) + bc2 * 2,
                 W + (size_t)(k0 + br) * DIM + bn + bc2);
        }
        cp_commit();
    };

    float acc[4][8][4];
#pragma unroll
    for (int i = 0; i < 4; i++)
#pragma unroll
        for (int j = 0; j < 8; j++)
#pragma unroll
            for (int k = 0; k < 4; k++) acc[i][j][k] = 0.0f;

    issue_stage(0, 0);
    issue_stage(1, 32);
    issue_stage(2, 64);

    for (int it = 0; it < NIT; it++) {
        cp_wait<2>();          // stage it%4 has landed (2 newer may fly)
        __syncthreads();       // all warps done with iter it-1 -> slot (it+3)%4 free

        if (it + 3 < NIT) issue_stage((it + 3) % NSTAGE, (it + 3) * 32);

        const int stg = it % NSTAGE;
        const uint32_t sa = smem_base + stg * STG_BYTES;
        const uint32_t sb = sa + A_BYTES;

#pragma unroll
        for (int kk = 0; kk < 32; kk += 16) {
            uint32_t af[4][4], bf[8][2];
#pragma unroll
            for (int mi = 0; mi < 4; mi++) {
                uint32_t off = (wm + mi * 16 + (lane & 15)) * (ASTR * 2)
                             + (kk + (lane >> 4) * 8) * 2;
                ldsm_x4(af[mi], sa + off);
            }
#pragma unroll
            for (int ni = 0; ni < 4; ni++) {
                uint32_t off = (kk + (lane & 15)) * (BSTR * 2)
                             + (wn + ni * 16 + (lane >> 4) * 8) * 2;
                uint32_t rb[4];
                ldsm_x4_t(rb, sb + off);
                bf[ni * 2][0] = rb[0]; bf[ni * 2][1] = rb[1];
                bf[ni * 2 + 1][0] = rb[2]; bf[ni * 2 + 1][1] = rb[3];
            }
#pragma unroll
            for (int mi = 0; mi < 4; mi++)
#pragma unroll
                for (int nj = 0; nj < 8; nj++)
                    mma_f16(acc[mi][nj], af[mi], bf[nj]);
        }
    }

    // Epilogue. c-frag: c0,c1 -> (row=lane>>2, col=(lane&3)*2+{0,1}); c2,c3 -> row+8.
    const int er = lane >> 2;
    const int ec = (lane & 3) * 2;
#pragma unroll
    for (int mi = 0; mi < 4; mi++) {
#pragma unroll
        for (int nj = 0; nj < 8; nj++) {
            int m0 = bm + wm + mi * 16 + er;
            int n0 = bn + wn + nj * 8 + ec;
            float v0 = acc[mi][nj][0], v1 = acc[mi][nj][1];
            float v2 = acc[mi][nj][2], v3 = acc[mi][nj][3];
            if (STAGE1) {
                float b0 = bias[n0], b1 = bias[n0 + 1];
                v0 = fmaxf(v0 + b0, 0.0f); v1 = fmaxf(v1 + b1, 0.0f);
                v2 = fmaxf(v2 + b0, 0.0f); v3 = fmaxf(v3 + b1, 0.0f);
                *(__half2*)&Oh[(size_t)m0 * DIM + n0]       = __floats2half2_rn(v0, v1);
                *(__half2*)&Oh[(size_t)(m0 + 8) * DIM + n0] = __floats2half2_rn(v2, v3);
            } else {
                *(float2*)&Of[(size_t)m0 * DIM + n0]       = make_float2(v0, v1);
                *(float2*)&Of[(size_t)(m0 + 8) * DIM + n0] = make_float2(v2, v3);
            }
        }
    }
}

__global__ __launch_bounds__(128, 2)
void stage1_kernel(const float* __restrict__ bs, const float* __restrict__ be)
{
    if (blockIdx.z == 0)
        gemm_body<true>(g_h, g_W, bs, g_S, nullptr);
    else
        gemm_body<true>(g_h, g_W + DIM * DIM, be, g_E, nullptr);
}

__global__ __launch_bounds__(128, 2)
void stage2_kernel()
{
    if (blockIdx.z == 0)
        gemm_body<false>(g_S, g_W + 2 * DIM * DIM, nullptr, nullptr, g_P);
    else
        gemm_body<false>(g_E, g_W + 3 * DIM * DIM, nullptr, nullptr, g_Q);
}

// ---------------------------------------------------------------------------
// Gather-add: out[b,n,:] = P[b, idx_s] + Q[b, idx_e] + bo   (span_idx int32)
// 4 rows per thread (8 independent gathered loads), streaming stores.
// ---------------------------------------------------------------------------
__global__ void gather_add_kernel(const int* __restrict__ span_idx,
                                  const float* __restrict__ bo,
                                  float* __restrict__ out)
{
    const int base = blockIdx.x * 16;
    const int ty = threadIdx.y;                 // 0..3
    const int t  = threadIdx.x;                 // 0..191
    float4 bv = __ldg(&((const float4*)bo)[t]);

    int   rows[4];
    const float4* pp[4];
    const float4* qq[4];
#pragma unroll
    for (int j = 0; j < 4; j++) {
        int r = base + j * 4 + ty;
        int b = r / NSPAN;
        int is = span_idx[r * 2], ie = span_idx[r * 2 + 1];
        rows[j] = r;
        pp[j] = (const float4*)(g_P + (size_t)(b * LEN + is) * DIM);
        qq[j] = (const float4*)(g_Q + (size_t)(b * LEN + ie) * DIM);
    }
    float4 pv[4], qv[4];
#pragma unroll
    for (int j = 0; j < 4; j++) pv[j] = pp[j][t];
#pragma unroll
    for (int j = 0; j < 4; j++) qv[j] = qq[j][t];
#pragma unroll
    for (int j = 0; j < 4; j++) {
        float4 o = make_float4(pv[j].x + qv[j].x + bv.x,
                               pv[j].y + qv[j].y + bv.y,
                               pv[j].z + qv[j].z + bv.z,
                               pv[j].w + qv[j].w + bv.w);
        __stcs(&((float4*)(out + (size_t)rows[j] * DIM))[t], o);
    }
}

extern "C" void kernel_launch(void* const* d_in, const int* in_sizes, int n_in,
                              void* d_out, int out_size)
{
    (void)in_sizes; (void)n_in; (void)out_size;
    const float* h    = (const float*)d_in[0];
    const int*   span = (const int*)d_in[1];
    const float* Ws   = (const float*)d_in[2];
    const float* bs   = (const float*)d_in[3];
    const float* We   = (const float*)d_in[4];
    const float* be   = (const float*)d_in[5];
    const float* Wo   = (const float*)d_in[6];
    const float* bo   = (const float*)d_in[7];
    float* out = (float*)d_out;

    static int smem_set = 0;
    if (!smem_set) {
        cudaFuncSetAttribute(stage1_kernel,
                             cudaFuncAttributeMaxDynamicSharedMemorySize, SMEM_TOTAL);
        cudaFuncSetAttribute(stage2_kernel,
                             cudaFuncAttributeMaxDynamicSharedMemorySize, SMEM_TOTAL);
        smem_set = 1;
    }

    hconv_kernel<<<3072, 256>>>(h);                    // 786432 float4s
    wconv_kernel<<<dim3(1152, 3), 256>>>(Ws, We, Wo);  // max region n4 = 294912

    dim3 gemm_grid(DIM / 128, MROWS / 128, 2);         // (6, 32, 2)
    stage1_kernel<<<gemm_grid, 128, SMEM_TOTAL>>>(bs, be);
    stage2_kernel<<<gemm_grid, 128, SMEM_TOTAL>>>();

    dim3 gblock(192, 4);
    gather_add_kernel<<<(BATCH * NSPAN) / 16, gblock>>>(span, bo, out);
}